// round 9
// baseline (speedup 1.0000x reference)
#include <cuda_runtime.h>
#include <cuda_bf16.h>
#include <cub/cub.cuh>
#include <cstdint>

typedef unsigned int u32;
typedef unsigned long long u64;

// Problem constants
constexpr int Bq = 2, Eq = 16, Hq = 160, Wq = 288, Nq = 12, Tq = 2;
constexpr int HW  = Hq * Wq;            // 46080
constexpr int P   = Tq * HW;            // 92160 pixels per instance
constexpr int BN  = Bq * Nq;            // 24 instances

constexpr int CPIX = 512;               // pixels per chunk (HW = 90*512)
constexpr int CH   = HW / CPIX;         // 90 chunks per (b,t)
constexpr int NBLK = Bq * Tq * CH;      // 360 blocks
constexpr int NCHK = Tq * CH;           // 180 partial chunks per instance
constexpr int ITER4 = CPIX / 128;       // 4 iters (32 lanes x 4 px)

constexpr int NB  = 1024;               // histogram bins over err in [0,2]
constexpr float FXS = 4096.0f;          // fixed-point scale 2^12
// hist packing: (pos<<47) | (neg<<30) | fxsum
//   pos,neg <= 92160 < 2^17; fxsum <= 7.6e8 < 2^30

constexpr int LTH = 256;                // losshist threads
constexpr int LIT = NB / LTH;           // 4 bins per thread

// -------- scratch (static device globals; no runtime allocation) --------
// layout: [bn][q][chunk] so finalize reads are chunk-contiguous (float4-able)
__device__ float g_part[BN * 33 * NCHK];
__device__ float g_w2[BN * Eq];         // var
__device__ float g_w1[BN * Eq];         // -2*var*mean
__device__ float g_c[BN];               // sum var*mean^2
__device__ float g_cnt[BN];
__device__ u64 g_hist[BN * NB];
__device__ float g_losspart[BN];
__device__ int g_done_s = 0;            // stats finalize counter
__device__ int g_done_l = 0;            // loss finalize counter

// -------- kernel 1: stats, warp-per-instance, float4 loads + finalize -----
__global__ void __launch_bounds__(384, 3) k_stats(
    const float* __restrict__ f1, const float* __restrict__ f2,
    const int* __restrict__ gt) {
    int blk = blockIdx.x;
    int b = blk / (Tq * CH);
    int r = blk % (Tq * CH);
    int t = r / CH, ch = r % CH;
    int hw0 = ch * CPIX;
    const float* fb = (t ? f2 : f1) + (size_t)b * Eq * HW + hw0;

    int w = threadIdx.x >> 5, lane = threadIdx.x & 31;   // w = instance 0..11
    int bn = b * Nq + w;
    const int4* gt4 = (const int4*)(gt + ((size_t)bn * Tq + t) * HW + hw0);

    float a[33];
#pragma unroll
    for (int q = 0; q < 33; q++) a[q] = 0.f;

#pragma unroll
    for (int it = 0; it < ITER4; it++) {
        int i4 = it * 32 + lane;
        int4 mm = gt4[i4];
        a[32] += (float)(mm.x + mm.y + mm.z + mm.w);
#pragma unroll
        for (int e = 0; e < Eq; e++) {
            float4 v = ((const float4*)(fb + (size_t)e * HW))[i4];
            float x0 = mm.x ? v.x : 0.f;
            float x1 = mm.y ? v.y : 0.f;
            float x2 = mm.z ? v.z : 0.f;
            float x3 = mm.w ? v.w : 0.f;
            a[e] += (x0 + x1) + (x2 + x3);
            a[16 + e] += fmaf(x0, v.x, fmaf(x1, v.y, fmaf(x2, v.z, x3 * v.w)));
        }
    }

#pragma unroll
    for (int q = 0; q < 33; q++)
#pragma unroll
        for (int off = 16; off > 0; off >>= 1)
            a[q] += __shfl_down_sync(0xFFFFFFFFu, a[q], off);

    if (lane == 0) {
        int ci = t * CH + ch;
#pragma unroll
        for (int q = 0; q < 33; q++)
            g_part[((size_t)bn * 33 + q) * NCHK + ci] = a[q];
    }

    // ---- last block finalizes mean/var for all 24 instances ----
    __shared__ bool last;
    __threadfence();
    __syncthreads();
    if (threadIdx.x == 0) {
        int d = atomicAdd(&g_done_s, 1);
        last = (d == NBLK - 1);
    }
    __syncthreads();
    if (!last) return;
    __threadfence();

    __shared__ float sums[BN][33];
    __shared__ float vm2[BN][Eq];
    for (int k = threadIdx.x; k < BN * 33; k += 384) {
        const float4* src = (const float4*)&g_part[(size_t)k * NCHK];
        float s = 0.f;
#pragma unroll 4
        for (int c = 0; c < NCHK / 4; c++) {
            float4 v = src[c];
            s += (v.x + v.y) + (v.z + v.w);
        }
        sums[k / 33][k % 33] = s;
    }
    __syncthreads();
    if (threadIdx.x < BN * Eq) {
        int ibn = threadIdx.x / Eq, e = threadIdx.x % Eq;
        float cnt = sums[ibn][32];
        float mean = sums[ibn][e] / cnt;
        float var  = (sums[ibn][16 + e] - cnt * mean * mean) / (cnt - 1.0f);
        g_w2[ibn * Eq + e] = var;
        g_w1[ibn * Eq + e] = -2.0f * var * mean;
        vm2[ibn][e] = var * mean * mean;
    }
    __syncthreads();
    if (threadIdx.x < BN) {
        float c = 0.f;
#pragma unroll
        for (int e = 0; e < Eq; e++) c += vm2[threadIdx.x][e];
        g_c[threadIdx.x] = c;
        g_cnt[threadIdx.x] = sums[threadIdx.x][32];
        if (threadIdx.x == 0) g_done_s = 0;    // reset for next replay
    }
}

// -------- kernel 2: fused error + histogram, warp-per-instance, float4 ----
__global__ void __launch_bounds__(384, 3) k_errhist(
    const float* __restrict__ f1, const float* __restrict__ f2,
    const int* __restrict__ gt) {
    int blk = blockIdx.x;
    int b = blk / (Tq * CH);
    int r = blk % (Tq * CH);
    int t = r / CH, ch = r % CH;
    int hw0 = ch * CPIX;
    const float* fb = (t ? f2 : f1) + (size_t)b * Eq * HW + hw0;

    int w = threadIdx.x >> 5, lane = threadIdx.x & 31;   // instance w
    int bn = b * Nq + w;
    const int4* gt4 = (const int4*)(gt + ((size_t)bn * Tq + t) * HW + hw0);
    size_t gb = (size_t)bn * NB;

    float w2[Eq], w1[Eq];
#pragma unroll
    for (int e = 0; e < Eq; e++) {
        w2[e] = g_w2[bn * Eq + e];
        w1[e] = g_w1[bn * Eq + e];
    }
    float cc = g_c[bn];

    u32 c0 = 0, cM = 0, s0 = 0, sM = 0;    // edge bins: (pos<<16|neg), fx sums

#pragma unroll
    for (int it = 0; it < ITER4; it++) {
        int i4 = it * 32 + lane;
        int4 mm = gt4[i4];
        float d0 = cc, d1 = cc, d2 = cc, d3 = cc;
#pragma unroll
        for (int e = 0; e < Eq; e++) {
            float4 v = ((const float4*)(fb + (size_t)e * HW))[i4];
            d0 = fmaf(v.x, fmaf(v.x, w2[e], w1[e]), d0);
            d1 = fmaf(v.y, fmaf(v.y, w2[e], w1[e]), d1);
            d2 = fmaf(v.z, fmaf(v.z, w2[e], w1[e]), d2);
            d3 = fmaf(v.w, fmaf(v.w, w2[e], w1[e]), d3);
        }
        float dd[4] = {d0, d1, d2, d3};
        int msk[4] = {mm.x, mm.y, mm.z, mm.w};
#pragma unroll
        for (int j = 0; j < 4; j++) {
            float logit = 2.0f * __expf(-0.5f * dd[j]) - 1.0f;
            float err = msk[j] ? (1.0f - logit) : (1.0f + logit);
            u32 fx = (u32)(err * FXS + 0.5f);
            int bin = (int)(err * (0.5f * NB));
            if (bin > NB - 1) bin = NB - 1;
            u32 pc = msk[j] ? 0x10000u : 1u;
            if (bin == 0)           { c0 += pc; s0 += fx; }
            else if (bin == NB - 1) { cM += pc; sM += fx; }
            else {
                u64 add = (msk[j] ? (1ull << 47) : (1ull << 30)) | (u64)fx;
                atomicAdd(&g_hist[gb + bin], add);
            }
        }
    }

    // warp-reduce edge accumulators, flush once per warp
#pragma unroll
    for (int off = 16; off > 0; off >>= 1) {
        c0 += __shfl_down_sync(0xFFFFFFFFu, c0, off);
        cM += __shfl_down_sync(0xFFFFFFFFu, cM, off);
        s0 += __shfl_down_sync(0xFFFFFFFFu, s0, off);
        sM += __shfl_down_sync(0xFFFFFFFFu, sM, off);
    }
    if (lane == 0) {
        if (c0)
            atomicAdd(&g_hist[gb + 0],
                ((u64)(c0 >> 16) << 47) | ((u64)(c0 & 0xFFFFu) << 30) | (u64)s0);
        if (cM)
            atomicAdd(&g_hist[gb + NB - 1],
                ((u64)(cM >> 16) << 47) | ((u64)(cM & 0xFFFFu) << 30) | (u64)sM);
    }
}

// -------- kernel 3: Lovász scan, block per instance, fused final ----------
__global__ void __launch_bounds__(LTH) k_losshist(float* __restrict__ out) {
    int bn = blockIdx.x;
    float gts = g_cnt[bn];
    int tid = threadIdx.x;
    size_t gbase = (size_t)bn * NB;

    // thread handles descending positions tid*LIT .. tid*LIT+LIT-1
    u32 pos[LIT], tot[LIT], fx[LIT];
    u64 tsum = 0ull;
#pragma unroll
    for (int i = 0; i < LIT; i++) {
        int bin = NB - 1 - (tid * LIT + i);
        u64 h = g_hist[gbase + bin];
        pos[i] = (u32)(h >> 47);
        u32 neg = (u32)(h >> 30) & 0x1FFFFu;
        tot[i] = pos[i] + neg;
        fx[i]  = (u32)(h & 0x3FFFFFFFull);
        tsum += ((u64)pos[i] << 32) | (u64)tot[i];
    }

    typedef cub::BlockScan<u64, LTH> Scan;
    __shared__ typename Scan::TempStorage ts;
    u64 excl;
    Scan(ts).ExclusiveSum(tsum, excl);

    u64 run = excl;
    float loss = 0.f;
#pragma unroll
    for (int i = 0; i < LIT; i++) {
        if (tot[i]) {
            float cA = (float)(u32)(run >> 32);
            float kA = (float)(u32)(run & 0xFFFFFFFFull);
            float cB = cA + (float)pos[i];
            float kB = kA + (float)tot[i];
            float JA = 1.0f - (gts - cA) / (gts + kA - cA);
            float JB = 1.0f - (gts - cB) / (gts + kB - cB);
            float err_rep = (float)fx[i] / (FXS * (float)tot[i]);
            loss += err_rep * (JB - JA);
        }
        run += ((u64)pos[i] << 32) | (u64)tot[i];
    }

    __shared__ float red[LTH];
    __syncthreads();
    red[tid] = loss;
    __syncthreads();
    for (int s = LTH / 2; s > 0; s >>= 1) {
        if (tid < s) red[tid] += red[tid + s];
        __syncthreads();
    }

    __shared__ bool is_last;
    if (tid == 0) {
        g_losspart[bn] = red[0];
        __threadfence();
        int done = atomicAdd(&g_done_l, 1);
        is_last = (done == BN - 1);
    }
    __syncthreads();
    if (is_last && tid == 0) {
        __threadfence();
        float s = 0.f;
#pragma unroll
        for (int i = 0; i < BN; i++) s += g_losspart[i];
        out[0] = s / (float)BN;
        g_done_l = 0;                   // reset for next graph replay
    }
}

extern "C" void kernel_launch(void* const* d_in, const int* in_sizes, int n_in,
                              void* d_out, int out_size) {
    const float* f1 = (const float*)d_in[0];
    const float* f2 = (const float*)d_in[1];
    const int*   gt = (const int*)d_in[2];
    float* out = (float*)d_out;

    void* hs = nullptr;
    cudaGetSymbolAddress(&hs, g_hist);
    cudaMemsetAsync(hs, 0, sizeof(u64) * BN * NB);

    k_stats<<<NBLK, 384>>>(f1, f2, gt);
    k_errhist<<<NBLK, 384>>>(f1, f2, gt);
    k_losshist<<<BN, LTH>>>(out);
}

// round 10
// speedup vs baseline: 1.2432x; 1.2432x over previous
#include <cuda_runtime.h>
#include <cuda_bf16.h>
#include <cstdint>

typedef unsigned int u32;
typedef unsigned long long u64;

// Problem constants
constexpr int Bq = 2, Eq = 16, Hq = 160, Wq = 288, Nq = 12, Tq = 2;
constexpr int HW  = Hq * Wq;            // 46080
constexpr int P   = Tq * HW;            // 92160
constexpr int BN  = Bq * Nq;            // 24 instances

constexpr int CPIX = 1280;              // pixels per chunk
constexpr int CH   = HW / CPIX;         // 36 chunks per (b,t)
constexpr int NBLK = Bq * Tq * CH;      // 144 blocks (<= SM count: co-resident)
constexpr int NCHK = Tq * CH;           // 72 partial chunks per instance
constexpr int ITER4 = CPIX / 128;       // 10 iters (32 lanes x 4 px)
constexpr int THREADS = 384;

constexpr int NB  = 1024;               // histogram bins over err in [0,2]
constexpr float FXS = 4096.0f;          // fixed-point 2^12
// hist packing: (pos<<47) | (neg<<30) | fxsum

constexpr int LTH = 256;                // loss scan lanes (of 384)
constexpr int LIT = NB / LTH;           // 4 bins per lane

// -------- scratch --------
__device__ float g_part[BN * NCHK * 33];
__device__ float g_w2[BN * Eq];
__device__ float g_w1[BN * Eq];
__device__ float g_c[BN];
__device__ float g_cnt[BN];
__device__ u64 g_hist[BN * NB];
__device__ float g_losspart[BN];
__device__ int g_sync = 0;              // monotonic grid barrier counter
__device__ int g_done_l = 0;            // loss finalize counter

__device__ __forceinline__ void gridbar(int phase) {
    __syncthreads();
    if (threadIdx.x == 0) {
        __threadfence();
        atomicAdd(&g_sync, 1);
        while (atomicAdd(&g_sync, 0) < phase * NBLK) __nanosleep(64);
    }
    __syncthreads();
}

__global__ void __launch_bounds__(THREADS) k_fused(
    const float* __restrict__ f1, const float* __restrict__ f2,
    const int* __restrict__ gt, float* __restrict__ out) {
    int blk = blockIdx.x;
    int tid = threadIdx.x;
    int b = blk / (Tq * CH);
    int r = blk % (Tq * CH);
    int t = r / CH, ch = r % CH;
    int hw0 = ch * CPIX;
    const float* fb = (t ? f2 : f1) + (size_t)b * Eq * HW + hw0;

    // replay-safe counter reset: no block can pass barrier1 (g_sync==NBLK)
    // until every block has run this CAS, so CAS(3*NBLK->0) never races.
    if (tid == 0) atomicCAS(&g_sync, 3 * NBLK, 0);
    __syncthreads();

    // zero hist slice (covered by barrier 1)
    for (int i = blk * THREADS + tid; i < BN * NB; i += NBLK * THREADS)
        g_hist[i] = 0ull;

    int w = tid >> 5, lane = tid & 31;  // warp w = instance w
    int bn = b * Nq + w;
    const int4* gt4 = (const int4*)(gt + ((size_t)bn * Tq + t) * HW + hw0);

    // ================= phase 1: stats =================
    {
        float a[33];
#pragma unroll
        for (int q = 0; q < 33; q++) a[q] = 0.f;

        for (int it = 0; it < ITER4; it++) {
            int i4 = it * 32 + lane;
            int4 mm = gt4[i4];
            a[32] += (float)(mm.x + mm.y + mm.z + mm.w);
#pragma unroll
            for (int e = 0; e < Eq; e++) {
                float4 v = ((const float4*)(fb + (size_t)e * HW))[i4];
                float x0 = mm.x ? v.x : 0.f;
                float x1 = mm.y ? v.y : 0.f;
                float x2 = mm.z ? v.z : 0.f;
                float x3 = mm.w ? v.w : 0.f;
                a[e] += (x0 + x1) + (x2 + x3);
                a[16 + e] += fmaf(x0, v.x, fmaf(x1, v.y, fmaf(x2, v.z, x3 * v.w)));
            }
        }
#pragma unroll
        for (int q = 0; q < 33; q++)
#pragma unroll
            for (int off = 16; off > 0; off >>= 1)
                a[q] += __shfl_down_sync(0xFFFFFFFFu, a[q], off);

        if (lane == 0) {
            float* dst = &g_part[((size_t)bn * NCHK + (t * CH + ch)) * 33];
#pragma unroll
            for (int q = 0; q < 33; q++) dst[q] = a[q];
        }
    }

    gridbar(1);

    // ================= phase 2: finalize (blocks 0..23) =================
    if (blk < BN) {
        __shared__ float fs[33][8];
        __shared__ float sums[33];
        __shared__ float vm2[Eq];
        int ibn = blk;
        if (tid < 264) {
            int q = tid >> 3, sl = tid & 7;   // q 0..32, slice 0..7
            float s = 0.f;
            for (int c = sl * 9; c < sl * 9 + 9; c++)
                s += g_part[((size_t)ibn * NCHK + c) * 33 + q];
            fs[q][sl] = s;
        }
        __syncthreads();
        if (tid < 33) {
            float s = 0.f;
#pragma unroll
            for (int sl = 0; sl < 8; sl++) s += fs[tid][sl];
            sums[tid] = s;
        }
        __syncthreads();
        float cnt = sums[32];
        if (tid < Eq) {
            float mean = sums[tid] / cnt;
            float var  = (sums[16 + tid] - cnt * mean * mean) / (cnt - 1.0f);
            g_w2[ibn * Eq + tid] = var;
            g_w1[ibn * Eq + tid] = -2.0f * var * mean;
            vm2[tid] = var * mean * mean;
        }
        __syncthreads();
        if (tid == 0) {
            float c = 0.f;
#pragma unroll
            for (int e = 0; e < Eq; e++) c += vm2[e];
            g_c[ibn] = c;
            g_cnt[ibn] = cnt;
        }
    }

    gridbar(2);

    // ================= phase 3: errhist (L1-warm feat window) =============
    {
        size_t gb = (size_t)bn * NB;
        float w2[Eq], w1[Eq];
#pragma unroll
        for (int e = 0; e < Eq; e++) {
            w2[e] = g_w2[bn * Eq + e];
            w1[e] = g_w1[bn * Eq + e];
        }
        float cc = g_c[bn];

        u32 c0 = 0, cM = 0, s0 = 0, sM = 0;

        for (int it = 0; it < ITER4; it++) {
            int i4 = it * 32 + lane;
            int4 mm = gt4[i4];
            float d0 = cc, d1 = cc, d2 = cc, d3 = cc;
#pragma unroll
            for (int e = 0; e < Eq; e++) {
                float4 v = ((const float4*)(fb + (size_t)e * HW))[i4];
                d0 = fmaf(v.x, fmaf(v.x, w2[e], w1[e]), d0);
                d1 = fmaf(v.y, fmaf(v.y, w2[e], w1[e]), d1);
                d2 = fmaf(v.z, fmaf(v.z, w2[e], w1[e]), d2);
                d3 = fmaf(v.w, fmaf(v.w, w2[e], w1[e]), d3);
            }
            float dd[4] = {d0, d1, d2, d3};
            int msk[4] = {mm.x, mm.y, mm.z, mm.w};
#pragma unroll
            for (int j = 0; j < 4; j++) {
                float logit = 2.0f * __expf(-0.5f * dd[j]) - 1.0f;
                float err = msk[j] ? (1.0f - logit) : (1.0f + logit);
                u32 fx = (u32)(err * FXS + 0.5f);
                int bin = (int)(err * (0.5f * NB));
                if (bin > NB - 1) bin = NB - 1;
                u32 pc = msk[j] ? 0x10000u : 1u;
                if (bin == 0)           { c0 += pc; s0 += fx; }
                else if (bin == NB - 1) { cM += pc; sM += fx; }
                else {
                    u64 add = (msk[j] ? (1ull << 47) : (1ull << 30)) | (u64)fx;
                    atomicAdd(&g_hist[gb + bin], add);
                }
            }
        }
#pragma unroll
        for (int off = 16; off > 0; off >>= 1) {
            c0 += __shfl_down_sync(0xFFFFFFFFu, c0, off);
            cM += __shfl_down_sync(0xFFFFFFFFu, cM, off);
            s0 += __shfl_down_sync(0xFFFFFFFFu, s0, off);
            sM += __shfl_down_sync(0xFFFFFFFFu, sM, off);
        }
        if (lane == 0) {
            if (c0)
                atomicAdd(&g_hist[gb + 0],
                    ((u64)(c0 >> 16) << 47) | ((u64)(c0 & 0xFFFFu) << 30) | (u64)s0);
            if (cM)
                atomicAdd(&g_hist[gb + NB - 1],
                    ((u64)(cM >> 16) << 47) | ((u64)(cM & 0xFFFFu) << 30) | (u64)sM);
        }
    }

    gridbar(3);
    if (tid == 0 && blk == 0) atomicCAS(&g_sync, 3 * NBLK, 3 * NBLK); // no-op keep

    // ================= phase 4: Lovász scan (blocks 0..23) ================
    if (blk >= BN) return;
    {
        int ibn = blk;
        float gts = g_cnt[ibn];
        size_t gbase = (size_t)ibn * NB;

        u32 pos[LIT], tot[LIT], fx[LIT];
        u64 tsum = 0ull;
        if (tid < LTH) {
#pragma unroll
            for (int i = 0; i < LIT; i++) {
                int bin = NB - 1 - (tid * LIT + i);
                u64 h = g_hist[gbase + bin];
                pos[i] = (u32)(h >> 47);
                u32 neg = (u32)(h >> 30) & 0x1FFFFu;
                tot[i] = pos[i] + neg;
                fx[i]  = (u32)(h & 0x3FFFFFFFull);
                tsum += ((u64)pos[i] << 32) | (u64)tot[i];
            }
        }

        // hand-rolled exclusive scan over 256 lanes (8 warps)
        __shared__ u64 wtot[8];
        u64 inc = tsum;
        if (tid < LTH) {
#pragma unroll
            for (int off = 1; off < 32; off <<= 1) {
                u64 n = __shfl_up_sync(0xFFFFFFFFu, inc, off);
                if (lane >= off) inc += n;
            }
            if (lane == 31) wtot[w] = inc;
        }
        __syncthreads();
        float loss = 0.f;
        if (tid < LTH) {
            u64 wpref = 0ull;
            for (int ww = 0; ww < w; ww++) wpref += wtot[ww];
            u64 run = wpref + inc - tsum;    // exclusive prefix
#pragma unroll
            for (int i = 0; i < LIT; i++) {
                if (tot[i]) {
                    float cA = (float)(u32)(run >> 32);
                    float kA = (float)(u32)(run & 0xFFFFFFFFull);
                    float cB = cA + (float)pos[i];
                    float kB = kA + (float)tot[i];
                    float JA = 1.0f - (gts - cA) / (gts + kA - cA);
                    float JB = 1.0f - (gts - cB) / (gts + kB - cB);
                    float err_rep = (float)fx[i] / (FXS * (float)tot[i]);
                    loss += err_rep * (JB - JA);
                }
                run += ((u64)pos[i] << 32) | (u64)tot[i];
            }
        }

        __shared__ float red[LTH];
        if (tid < LTH) red[tid] = loss;
        __syncthreads();
        for (int s = LTH / 2; s > 0; s >>= 1) {
            if (tid < s) red[tid] += red[tid + s];
            __syncthreads();
        }

        __shared__ bool is_last;
        if (tid == 0) {
            g_losspart[ibn] = red[0];
            __threadfence();
            int done = atomicAdd(&g_done_l, 1);
            is_last = (done == BN - 1);
        }
        __syncthreads();
        if (is_last && tid == 0) {
            __threadfence();
            float s = 0.f;
#pragma unroll
            for (int i = 0; i < BN; i++) s += g_losspart[i];
            out[0] = s / (float)BN;
            g_done_l = 0;               // reset for next replay
        }
    }
}

extern "C" void kernel_launch(void* const* d_in, const int* in_sizes, int n_in,
                              void* d_out, int out_size) {
    const float* f1 = (const float*)d_in[0];
    const float* f2 = (const float*)d_in[1];
    const int*   gt = (const int*)d_in[2];
    float* out = (float*)d_out;
    k_fused<<<NBLK, THREADS>>>(f1, f2, gt, out);
}